// round 10
// baseline (speedup 1.0000x reference)
#include <cuda_runtime.h>
#include <cuda_bf16.h>
#include <cstdint>

#define DD 64

#define MAX_E_TOTAL 2000000      // E_KG + E_UI
#define MAX_SEG     160000       // N_ENT + N_USR
#define MAX_AGG     (MAX_SEG * DD)

// -------- device scratch (no allocations allowed) --------
// g_accum: zero-initialized at module load; k_tail re-zeros it every call,
// so every kernel_launch invocation sees it as zeros (deterministic).
static __device__ float g_accum[MAX_AGG];
static __device__ float g_score[MAX_E_TOTAL];   // ex = exp(score)
static __device__ float g_ssum [MAX_SEG];

__device__ __forceinline__ void red_add_v4(float* p, float4 v) {
    asm volatile("red.global.add.v4.f32 [%0], {%1,%2,%3,%4};"
                 :: "l"(p), "f"(v.x), "f"(v.y), "f"(v.z), "f"(v.w) : "memory");
}
__device__ __forceinline__ float dot4(float4 a, float4 b) {
    return a.x * b.x + a.y * b.y + a.z * b.z + a.w * b.w;
}
__device__ __forceinline__ float dot4x3(float4 a, float4 b, float4 c) {
    return a.x * b.x * c.x + a.y * b.y * c.y + a.z * b.z * c.z + a.w * b.w * c.w;
}

// ---------------------------------------------------------------------------
// K0: init — zero segment sums only (accum is self-cleaned by k_tail).
// ---------------------------------------------------------------------------
__global__ void k_init(int n_seg) {
    int i = blockIdx.x * blockDim.x + threadIdx.x;
    if (i < n_seg) g_ssum[i] = 0.0f;
}

// ---------------------------------------------------------------------------
// K1: FUSED heavy pass. 8 threads per edge, 2x float4 per thread,
//   persistent grid-stride; rel/inter staged in smem; REDs into g_accum.
// ---------------------------------------------------------------------------
__global__ void __launch_bounds__(256)
k_fused(const float4* __restrict__ ent4,
        const float4* __restrict__ usr4,
        const float4* __restrict__ inter4,
        const float4* __restrict__ rel4,
        const int* __restrict__ eidx,      // [2, E_KG]
        const int* __restrict__ etype,     // [E_KG]
        const int* __restrict__ uidx,      // [E_UI]
        const int* __restrict__ iidx,      // [E_UI]
        const int* __restrict__ itype,     // [E_UI]
        int E_KG, int E_UI, int N_ENT, int N_USR,
        int N_REL, int N_ITYPE)
{
    __shared__ float4 s_rel[16 * 16];
    __shared__ float4 s_inter[8 * 16];

    for (int j = threadIdx.x; j < N_REL * 16; j += blockDim.x)
        s_rel[j] = rel4[j];
    for (int j = threadIdx.x; j < N_ITYPE * 16; j += blockDim.x)
        s_inter[j] = inter4[j];
    __syncthreads();

    int T = E_KG + E_UI;
    int c = threadIdx.x & 7;
    int e0    = (int)(((long long)blockIdx.x * blockDim.x + threadIdx.x) >> 3);
    int estep = (int)(((long long)gridDim.x * blockDim.x) >> 3);

    float* ent_agg = g_accum;
    float* usr_agg = g_accum + (long long)N_ENT * DD;

    for (int e = e0; e < T; e += estep) {
        if (e < E_KG) {
            int head = eidx[e];
            int tail = eidx[E_KG + e];
            int rt   = etype[e] - 1;
            const float4* nrow = ent4 + (long long)tail * 16;
            float4 nv0 = nrow[c];
            float4 nv1 = nrow[c + 8];
            float4 rv0 = s_rel[rt * 16 + c];
            float4 rv1 = s_rel[rt * 16 + c + 8];
            float p = dot4(nv0, rv0) + dot4(nv1, rv1);
            #pragma unroll
            for (int o = 4; o > 0; o >>= 1)
                p += __shfl_xor_sync(0xffffffffu, p, o);
            float ex = __expf(p * 0.125f);
            float* dst = ent_agg + (long long)head * DD;
            red_add_v4(dst + c * 4,
                       make_float4(nv0.x * ex, nv0.y * ex, nv0.z * ex, nv0.w * ex));
            red_add_v4(dst + (c + 8) * 4,
                       make_float4(nv1.x * ex, nv1.y * ex, nv1.z * ex, nv1.w * ex));
            if (c == 0) {
                g_score[e] = ex;
                atomicAdd(&g_ssum[head], ex);
            }
        } else {
            int i  = e - E_KG;
            int u  = uidx[i];
            int it = iidx[i];
            int ty = itype[i];
            const float4* irow = ent4 + (long long)it * 16;
            const float4* urow = usr4 + (long long)u * 16;
            float4 iv0 = irow[c];
            float4 iv1 = irow[c + 8];
            float4 uv0 = urow[c];
            float4 uv1 = urow[c + 8];
            float4 tv0 = s_inter[ty * 16 + c];
            float4 tv1 = s_inter[ty * 16 + c + 8];
            float p = dot4x3(iv0, uv0, tv0) + dot4x3(iv1, uv1, tv1);
            #pragma unroll
            for (int o = 4; o > 0; o >>= 1)
                p += __shfl_xor_sync(0xffffffffu, p, o);
            float ex = __expf(p);
            float* dst = usr_agg + (long long)u * DD;
            red_add_v4(dst + c * 4,
                       make_float4(iv0.x * ex, iv0.y * ex, iv0.z * ex, iv0.w * ex));
            red_add_v4(dst + (c + 8) * 4,
                       make_float4(iv1.x * ex, iv1.y * ex, iv1.z * ex, iv1.w * ex));
            if (c == 0) {
                g_score[e] = ex;
                atomicAdd(&g_ssum[N_ENT + u], ex);
            }
        }
    }
}

// ---------------------------------------------------------------------------
// K2: merged tail.
//   [0, n4):    out = accum * inv(ssum); re-zero accum (scratch self-clean).
//   [n4, n4+T): per-edge weights w = ex/ssum -> att, w1.
// d_out is never pre-zeroed: every output element is written here.
// ---------------------------------------------------------------------------
__global__ void k_tail(float4* __restrict__ out4, int n4,
                       const int* __restrict__ eidx,
                       const int* __restrict__ uidx,
                       float* __restrict__ out,
                       int E_KG, int E_UI, int N_ENT, int N_USR)
{
    int i = blockIdx.x * blockDim.x + threadIdx.x;
    if (i < n4) {
        int seg = i >> 4;
        float s = g_ssum[seg];
        float inv = (s > 0.0f) ? __frcp_rn(s) : 0.0f;
        float4* acc4 = (float4*)g_accum;
        float4 v = acc4[i];
        acc4[i] = make_float4(0.f, 0.f, 0.f, 0.f);   // self-clean for next call
        v.x *= inv; v.y *= inv; v.z *= inv; v.w *= inv;
        out4[i] = v;
    } else {
        int e = i - n4;
        int T = E_KG + E_UI;
        if (e >= T) return;
        float* att_out = out + (long long)(N_ENT + N_USR) * DD;
        float* w1_out  = att_out + E_UI;
        if (e < E_KG) {
            int head = eidx[e];
            w1_out[e] = g_score[e] * __frcp_rn(g_ssum[head]);
        } else {
            int j = e - E_KG;
            int u = uidx[j];
            att_out[j] = g_score[e] * __frcp_rn(g_ssum[N_ENT + u]);
        }
    }
}

// ---------------------------------------------------------------------------
extern "C" void kernel_launch(void* const* d_in, const int* in_sizes, int n_in,
                              void* d_out, int out_size)
{
    const float4* ent4   = (const float4*)d_in[0];
    const float4* usr4   = (const float4*)d_in[1];
    const float4* inter4 = (const float4*)d_in[2];
    const float4* rel4   = (const float4*)d_in[3];
    const int* eidx  = (const int*)d_in[4];
    const int* etype = (const int*)d_in[5];
    const int* uidx  = (const int*)d_in[6];
    const int* iidx  = (const int*)d_in[7];
    const int* itype = (const int*)d_in[8];
    float* out = (float*)d_out;

    int N_ENT   = in_sizes[0] / DD;
    int N_USR   = in_sizes[1] / DD;
    int N_ITYPE = in_sizes[2] / DD;
    int N_REL   = in_sizes[3] / DD;
    int E_KG    = in_sizes[5];
    int E_UI    = in_sizes[6];
    int T = E_KG + E_UI;
    int n_agg = (N_ENT + N_USR) * DD;
    int n_seg = N_ENT + N_USR;
    int n4 = n_agg / 4;

    const int B = 256;

    k_init<<<(n_seg + B - 1) / B, B>>>(n_seg);

    // persistent single-wave grid: 148 SMs x 8 blocks
    k_fused<<<1184, B>>>(ent4, usr4, inter4, rel4,
                         eidx, etype, uidx, iidx, itype,
                         E_KG, E_UI, N_ENT, N_USR, N_REL, N_ITYPE);

    int tail_work = n4 + T;
    k_tail<<<(tail_work + B - 1) / B, B>>>((float4*)out, n4, eidx, uidx, out,
                                           E_KG, E_UI, N_ENT, N_USR);
}

// round 11
// speedup vs baseline: 1.2397x; 1.2397x over previous
#include <cuda_runtime.h>
#include <cuda_bf16.h>
#include <cstdint>

#define DD 64

#define MAX_E_TOTAL 2000000      // E_KG + E_UI
#define MAX_SEG     160000       // N_ENT + N_USR

// -------- device scratch (no allocations allowed) --------
static __device__ float g_score[MAX_E_TOTAL];   // ex = exp(score)
static __device__ float g_ssum [MAX_SEG];

// NOTE: no "memory" clobber — REDs are fire-and-forget; only k_tail (next
// kernel) reads the accumulators, and register dataflow orders each RED
// after its own source loads. This lets ptxas hoist the next iteration's
// gathers above this iteration's scatter (cross-iteration MLP).
__device__ __forceinline__ void red_add_v4(float* p, float4 v) {
    asm volatile("red.global.add.v4.f32 [%0], {%1,%2,%3,%4};"
                 :: "l"(p), "f"(v.x), "f"(v.y), "f"(v.z), "f"(v.w));
}
__device__ __forceinline__ float dot4(float4 a, float4 b) {
    return a.x * b.x + a.y * b.y + a.z * b.z + a.w * b.w;
}
__device__ __forceinline__ float dot4x3(float4 a, float4 b, float4 c) {
    return a.x * b.x * c.x + a.y * b.y * c.y + a.z * b.z * c.z + a.w * b.w * c.w;
}

// ---------------------------------------------------------------------------
// K0: init — zero agg outputs (float4) and segment sums
// ---------------------------------------------------------------------------
__global__ void k_init(float4* out4, int n4, int n_seg) {
    int i = blockIdx.x * blockDim.x + threadIdx.x;
    int stride = gridDim.x * blockDim.x;
    float4 z = make_float4(0.f, 0.f, 0.f, 0.f);
    for (int j = i; j < n4; j += stride) out4[j] = z;
    for (int j = i; j < n_seg; j += stride) g_ssum[j] = 0.0f;
}

// ---------------------------------------------------------------------------
// K1: FUSED heavy pass. 8 threads per edge, 2x float4 per thread.
//   Persistent grid; TWO branch-free grid-stride phases (KG then UI) so the
//   hot loops are unrollable; unroll 2 + clobber-free REDs give ptxas two
//   independent edge chains in flight per thread.
// ---------------------------------------------------------------------------
__global__ void __launch_bounds__(256)
k_fused(const float4* __restrict__ ent4,
        const float4* __restrict__ usr4,
        const float4* __restrict__ inter4,
        const float4* __restrict__ rel4,
        const int* __restrict__ eidx,      // [2, E_KG]
        const int* __restrict__ etype,     // [E_KG]
        const int* __restrict__ uidx,      // [E_UI]
        const int* __restrict__ iidx,      // [E_UI]
        const int* __restrict__ itype,     // [E_UI]
        float* __restrict__ out,
        int E_KG, int E_UI, int N_ENT, int N_USR,
        int N_REL, int N_ITYPE)
{
    __shared__ float4 s_rel[16 * 16];
    __shared__ float4 s_inter[8 * 16];

    for (int j = threadIdx.x; j < N_REL * 16; j += blockDim.x)
        s_rel[j] = rel4[j];
    for (int j = threadIdx.x; j < N_ITYPE * 16; j += blockDim.x)
        s_inter[j] = inter4[j];
    __syncthreads();

    int c = threadIdx.x & 7;
    int g0    = (int)(((long long)blockIdx.x * blockDim.x + threadIdx.x) >> 3);
    int gstep = (int)(((long long)gridDim.x * blockDim.x) >> 3);

    float* ent_agg = out;
    float* usr_agg = out + (long long)N_ENT * DD;

    // ---- Phase 1: KG edges (branch-free loop) ----
    #pragma unroll 2
    for (int e = g0; e < E_KG; e += gstep) {
        int head = eidx[e];
        int tail = eidx[E_KG + e];
        int rt   = etype[e] - 1;
        const float4* nrow = ent4 + (long long)tail * 16;
        float4 nv0 = nrow[c];
        float4 nv1 = nrow[c + 8];
        float4 rv0 = s_rel[rt * 16 + c];
        float4 rv1 = s_rel[rt * 16 + c + 8];
        float p = dot4(nv0, rv0) + dot4(nv1, rv1);
        #pragma unroll
        for (int o = 4; o > 0; o >>= 1)
            p += __shfl_xor_sync(0xffffffffu, p, o);
        float ex = __expf(p * 0.125f);
        float* dst = ent_agg + (long long)head * DD;
        red_add_v4(dst + c * 4,
                   make_float4(nv0.x * ex, nv0.y * ex, nv0.z * ex, nv0.w * ex));
        red_add_v4(dst + (c + 8) * 4,
                   make_float4(nv1.x * ex, nv1.y * ex, nv1.z * ex, nv1.w * ex));
        if (c == 0) {
            g_score[e] = ex;
            atomicAdd(&g_ssum[head], ex);
        }
    }

    // ---- Phase 2: UI edges (branch-free loop) ----
    #pragma unroll 2
    for (int i = g0; i < E_UI; i += gstep) {
        int u  = uidx[i];
        int it = iidx[i];
        int ty = itype[i];
        const float4* irow = ent4 + (long long)it * 16;
        const float4* urow = usr4 + (long long)u * 16;
        float4 iv0 = irow[c];
        float4 iv1 = irow[c + 8];
        float4 uv0 = urow[c];
        float4 uv1 = urow[c + 8];
        float4 tv0 = s_inter[ty * 16 + c];
        float4 tv1 = s_inter[ty * 16 + c + 8];
        float p = dot4x3(iv0, uv0, tv0) + dot4x3(iv1, uv1, tv1);
        #pragma unroll
        for (int o = 4; o > 0; o >>= 1)
            p += __shfl_xor_sync(0xffffffffu, p, o);
        float ex = __expf(p);
        float* dst = usr_agg + (long long)u * DD;
        red_add_v4(dst + c * 4,
                   make_float4(iv0.x * ex, iv0.y * ex, iv0.z * ex, iv0.w * ex));
        red_add_v4(dst + (c + 8) * 4,
                   make_float4(iv1.x * ex, iv1.y * ex, iv1.z * ex, iv1.w * ex));
        if (c == 0) {
            g_score[E_KG + i] = ex;
            atomicAdd(&g_ssum[N_ENT + u], ex);
        }
    }
}

// ---------------------------------------------------------------------------
// K2: merged tail. [0, n4): normalize agg rows; [n4, n4+T): edge weights.
// ---------------------------------------------------------------------------
__global__ void k_tail(float4* __restrict__ out4, int n4,
                       const int* __restrict__ eidx,
                       const int* __restrict__ uidx,
                       float* __restrict__ out,
                       int E_KG, int E_UI, int N_ENT, int N_USR)
{
    int i = blockIdx.x * blockDim.x + threadIdx.x;
    if (i < n4) {
        int seg = i >> 4;
        float s = g_ssum[seg];
        float inv = (s > 0.0f) ? __frcp_rn(s) : 0.0f;
        float4 v = out4[i];
        v.x *= inv; v.y *= inv; v.z *= inv; v.w *= inv;
        out4[i] = v;
    } else {
        int e = i - n4;
        int T = E_KG + E_UI;
        if (e >= T) return;
        float* att_out = out + (long long)(N_ENT + N_USR) * DD;
        float* w1_out  = att_out + E_UI;
        if (e < E_KG) {
            int head = eidx[e];
            w1_out[e] = g_score[e] * __frcp_rn(g_ssum[head]);
        } else {
            int j = e - E_KG;
            int u = uidx[j];
            att_out[j] = g_score[e] * __frcp_rn(g_ssum[N_ENT + u]);
        }
    }
}

// ---------------------------------------------------------------------------
extern "C" void kernel_launch(void* const* d_in, const int* in_sizes, int n_in,
                              void* d_out, int out_size)
{
    const float4* ent4   = (const float4*)d_in[0];
    const float4* usr4   = (const float4*)d_in[1];
    const float4* inter4 = (const float4*)d_in[2];
    const float4* rel4   = (const float4*)d_in[3];
    const int* eidx  = (const int*)d_in[4];
    const int* etype = (const int*)d_in[5];
    const int* uidx  = (const int*)d_in[6];
    const int* iidx  = (const int*)d_in[7];
    const int* itype = (const int*)d_in[8];
    float* out = (float*)d_out;

    int N_ENT   = in_sizes[0] / DD;
    int N_USR   = in_sizes[1] / DD;
    int N_ITYPE = in_sizes[2] / DD;
    int N_REL   = in_sizes[3] / DD;
    int E_KG    = in_sizes[5];
    int E_UI    = in_sizes[6];
    int T = E_KG + E_UI;
    int n_agg = (N_ENT + N_USR) * DD;
    int n_seg = N_ENT + N_USR;
    int n4 = n_agg / 4;

    const int B = 256;

    k_init<<<4096, B>>>((float4*)out, n4, n_seg);

    // persistent grid, two balanced phases per block
    k_fused<<<2048, B>>>(ent4, usr4, inter4, rel4,
                         eidx, etype, uidx, iidx, itype,
                         out, E_KG, E_UI, N_ENT, N_USR, N_REL, N_ITYPE);

    int tail_work = n4 + T;
    k_tail<<<(tail_work + B - 1) / B, B>>>((float4*)out, n4, eidx, uidx, out,
                                           E_KG, E_UI, N_ENT, N_USR);
}

// round 12
// speedup vs baseline: 1.2456x; 1.0047x over previous
#include <cuda_runtime.h>
#include <cuda_bf16.h>
#include <cstdint>

#define DD 64

#define MAX_E_TOTAL 2000000      // E_KG + E_UI
#define MAX_SEG     160000       // N_ENT + N_USR

// -------- device scratch (no allocations allowed) --------
static __device__ float g_score[MAX_E_TOTAL];   // ex = exp(score)
static __device__ float g_ssum [MAX_SEG];

// NOTE: no "memory" clobber — REDs are fire-and-forget; only k_tail (next
// kernel) reads the accumulators, and register dataflow orders each RED
// after its own source loads. This lets ptxas hoist the next iteration's
// gathers above this iteration's scatter (cross-iteration MLP).
__device__ __forceinline__ void red_add_v4(float* p, float4 v) {
    asm volatile("red.global.add.v4.f32 [%0], {%1,%2,%3,%4};"
                 :: "l"(p), "f"(v.x), "f"(v.y), "f"(v.z), "f"(v.w));
}
__device__ __forceinline__ float dot4(float4 a, float4 b) {
    return a.x * b.x + a.y * b.y + a.z * b.z + a.w * b.w;
}
__device__ __forceinline__ float dot4x3(float4 a, float4 b, float4 c) {
    return a.x * b.x * c.x + a.y * b.y * c.y + a.z * b.z * c.z + a.w * b.w * c.w;
}

// ---------------------------------------------------------------------------
// K0: init — zero agg outputs (float4) and segment sums
// ---------------------------------------------------------------------------
__global__ void k_init(float4* out4, int n4, int n_seg) {
    int i = blockIdx.x * blockDim.x + threadIdx.x;
    int stride = gridDim.x * blockDim.x;
    float4 z = make_float4(0.f, 0.f, 0.f, 0.f);
    for (int j = i; j < n4; j += stride) out4[j] = z;
    for (int j = i; j < n_seg; j += stride) g_ssum[j] = 0.0f;
}

// ---------------------------------------------------------------------------
// K1: FUSED heavy pass. 8 threads per edge, 2x float4 per thread.
//   Persistent grid; TWO branch-free grid-stride phases (KG then UI) so the
//   hot loops are unrollable; unroll 2 + clobber-free REDs give ptxas two
//   independent edge chains in flight per thread.
// ---------------------------------------------------------------------------
__global__ void __launch_bounds__(256)
k_fused(const float4* __restrict__ ent4,
        const float4* __restrict__ usr4,
        const float4* __restrict__ inter4,
        const float4* __restrict__ rel4,
        const int* __restrict__ eidx,      // [2, E_KG]
        const int* __restrict__ etype,     // [E_KG]
        const int* __restrict__ uidx,      // [E_UI]
        const int* __restrict__ iidx,      // [E_UI]
        const int* __restrict__ itype,     // [E_UI]
        float* __restrict__ out,
        int E_KG, int E_UI, int N_ENT, int N_USR,
        int N_REL, int N_ITYPE)
{
    __shared__ float4 s_rel[16 * 16];
    __shared__ float4 s_inter[8 * 16];

    for (int j = threadIdx.x; j < N_REL * 16; j += blockDim.x)
        s_rel[j] = rel4[j];
    for (int j = threadIdx.x; j < N_ITYPE * 16; j += blockDim.x)
        s_inter[j] = inter4[j];
    __syncthreads();

    int c = threadIdx.x & 7;
    int g0    = (int)(((long long)blockIdx.x * blockDim.x + threadIdx.x) >> 3);
    int gstep = (int)(((long long)gridDim.x * blockDim.x) >> 3);

    float* ent_agg = out;
    float* usr_agg = out + (long long)N_ENT * DD;

    // ---- Phase 1: KG edges (branch-free loop) ----
    #pragma unroll 2
    for (int e = g0; e < E_KG; e += gstep) {
        int head = eidx[e];
        int tail = eidx[E_KG + e];
        int rt   = etype[e] - 1;
        const float4* nrow = ent4 + (long long)tail * 16;
        float4 nv0 = nrow[c];
        float4 nv1 = nrow[c + 8];
        float4 rv0 = s_rel[rt * 16 + c];
        float4 rv1 = s_rel[rt * 16 + c + 8];
        float p = dot4(nv0, rv0) + dot4(nv1, rv1);
        #pragma unroll
        for (int o = 4; o > 0; o >>= 1)
            p += __shfl_xor_sync(0xffffffffu, p, o);
        float ex = __expf(p * 0.125f);
        float* dst = ent_agg + (long long)head * DD;
        red_add_v4(dst + c * 4,
                   make_float4(nv0.x * ex, nv0.y * ex, nv0.z * ex, nv0.w * ex));
        red_add_v4(dst + (c + 8) * 4,
                   make_float4(nv1.x * ex, nv1.y * ex, nv1.z * ex, nv1.w * ex));
        if (c == 0) {
            g_score[e] = ex;
            atomicAdd(&g_ssum[head], ex);
        }
    }

    // ---- Phase 2: UI edges (branch-free loop) ----
    #pragma unroll 2
    for (int i = g0; i < E_UI; i += gstep) {
        int u  = uidx[i];
        int it = iidx[i];
        int ty = itype[i];
        const float4* irow = ent4 + (long long)it * 16;
        const float4* urow = usr4 + (long long)u * 16;
        float4 iv0 = irow[c];
        float4 iv1 = irow[c + 8];
        float4 uv0 = urow[c];
        float4 uv1 = urow[c + 8];
        float4 tv0 = s_inter[ty * 16 + c];
        float4 tv1 = s_inter[ty * 16 + c + 8];
        float p = dot4x3(iv0, uv0, tv0) + dot4x3(iv1, uv1, tv1);
        #pragma unroll
        for (int o = 4; o > 0; o >>= 1)
            p += __shfl_xor_sync(0xffffffffu, p, o);
        float ex = __expf(p);
        float* dst = usr_agg + (long long)u * DD;
        red_add_v4(dst + c * 4,
                   make_float4(iv0.x * ex, iv0.y * ex, iv0.z * ex, iv0.w * ex));
        red_add_v4(dst + (c + 8) * 4,
                   make_float4(iv1.x * ex, iv1.y * ex, iv1.z * ex, iv1.w * ex));
        if (c == 0) {
            g_score[E_KG + i] = ex;
            atomicAdd(&g_ssum[N_ENT + u], ex);
        }
    }
}

// ---------------------------------------------------------------------------
// K2: merged tail. [0, n4): normalize agg rows; [n4, n4+T): edge weights.
// ---------------------------------------------------------------------------
__global__ void k_tail(float4* __restrict__ out4, int n4,
                       const int* __restrict__ eidx,
                       const int* __restrict__ uidx,
                       float* __restrict__ out,
                       int E_KG, int E_UI, int N_ENT, int N_USR)
{
    int i = blockIdx.x * blockDim.x + threadIdx.x;
    if (i < n4) {
        int seg = i >> 4;
        float s = g_ssum[seg];
        float inv = (s > 0.0f) ? __frcp_rn(s) : 0.0f;
        float4 v = out4[i];
        v.x *= inv; v.y *= inv; v.z *= inv; v.w *= inv;
        out4[i] = v;
    } else {
        int e = i - n4;
        int T = E_KG + E_UI;
        if (e >= T) return;
        float* att_out = out + (long long)(N_ENT + N_USR) * DD;
        float* w1_out  = att_out + E_UI;
        if (e < E_KG) {
            int head = eidx[e];
            w1_out[e] = g_score[e] * __frcp_rn(g_ssum[head]);
        } else {
            int j = e - E_KG;
            int u = uidx[j];
            att_out[j] = g_score[e] * __frcp_rn(g_ssum[N_ENT + u]);
        }
    }
}

// ---------------------------------------------------------------------------
extern "C" void kernel_launch(void* const* d_in, const int* in_sizes, int n_in,
                              void* d_out, int out_size)
{
    const float4* ent4   = (const float4*)d_in[0];
    const float4* usr4   = (const float4*)d_in[1];
    const float4* inter4 = (const float4*)d_in[2];
    const float4* rel4   = (const float4*)d_in[3];
    const int* eidx  = (const int*)d_in[4];
    const int* etype = (const int*)d_in[5];
    const int* uidx  = (const int*)d_in[6];
    const int* iidx  = (const int*)d_in[7];
    const int* itype = (const int*)d_in[8];
    float* out = (float*)d_out;

    int N_ENT   = in_sizes[0] / DD;
    int N_USR   = in_sizes[1] / DD;
    int N_ITYPE = in_sizes[2] / DD;
    int N_REL   = in_sizes[3] / DD;
    int E_KG    = in_sizes[5];
    int E_UI    = in_sizes[6];
    int T = E_KG + E_UI;
    int n_agg = (N_ENT + N_USR) * DD;
    int n_seg = N_ENT + N_USR;
    int n4 = n_agg / 4;

    const int B = 256;

    k_init<<<4096, B>>>((float4*)out, n4, n_seg);

    // persistent grid, two balanced phases per block
    k_fused<<<2048, B>>>(ent4, usr4, inter4, rel4,
                         eidx, etype, uidx, iidx, itype,
                         out, E_KG, E_UI, N_ENT, N_USR, N_REL, N_ITYPE);

    int tail_work = n4 + T;
    k_tail<<<(tail_work + B - 1) / B, B>>>((float4*)out, n4, eidx, uidx, out,
                                           E_KG, E_UI, N_ENT, N_USR);
}

// round 14
// speedup vs baseline: 1.3206x; 1.0602x over previous
#include <cuda_runtime.h>
#include <cuda_bf16.h>
#include <cstdint>

#define DD 64

#define MAX_E_TOTAL 2000000      // E_KG + E_UI
#define MAX_SEG     160000       // N_ENT + N_USR

// -------- device scratch (no allocations allowed) --------
static __device__ float g_score[MAX_E_TOTAL];   // ex = exp(score)
static __device__ float g_ssum [MAX_SEG];

// NOTE: no "memory" clobber — REDs are fire-and-forget; only k_tail (next
// kernel) reads the accumulators, and register dataflow orders each RED
// after its own source loads. This lets ptxas hoist the next iteration's
// gathers above this iteration's scatter (cross-iteration MLP).
__device__ __forceinline__ void red_add_v4(float* p, float4 v) {
    asm volatile("red.global.add.v4.f32 [%0], {%1,%2,%3,%4};"
                 :: "l"(p), "f"(v.x), "f"(v.y), "f"(v.z), "f"(v.w));
}
__device__ __forceinline__ float dot4(float4 a, float4 b) {
    return a.x * b.x + a.y * b.y + a.z * b.z + a.w * b.w;
}
__device__ __forceinline__ float dot4x3(float4 a, float4 b, float4 c) {
    return a.x * b.x * c.x + a.y * b.y * c.y + a.z * b.z * c.z + a.w * b.w * c.w;
}

// ---------------------------------------------------------------------------
// K0: init — zero agg outputs (float4) and segment sums
// ---------------------------------------------------------------------------
__global__ void k_init(float4* out4, int n4, int n_seg) {
    int i = blockIdx.x * blockDim.x + threadIdx.x;
    int stride = gridDim.x * blockDim.x;
    float4 z = make_float4(0.f, 0.f, 0.f, 0.f);
    for (int j = i; j < n4; j += stride) out4[j] = z;
    for (int j = i; j < n_seg; j += stride) g_ssum[j] = 0.0f;
}

// ---------------------------------------------------------------------------
// K1: FUSED heavy pass. 8 threads per edge, 2x float4 per thread.
//   Persistent grid; TWO branch-free grid-stride phases (KG then UI) so the
//   hot loops are unrollable; unroll 2 + clobber-free REDs give ptxas two
//   independent edge chains in flight per thread.
// ---------------------------------------------------------------------------
__global__ void __launch_bounds__(256)
k_fused(const float4* __restrict__ ent4,
        const float4* __restrict__ usr4,
        const float4* __restrict__ inter4,
        const float4* __restrict__ rel4,
        const int* __restrict__ eidx,      // [2, E_KG]
        const int* __restrict__ etype,     // [E_KG]
        const int* __restrict__ uidx,      // [E_UI]
        const int* __restrict__ iidx,      // [E_UI]
        const int* __restrict__ itype,     // [E_UI]
        float* __restrict__ out,
        int E_KG, int E_UI, int N_ENT, int N_USR,
        int N_REL, int N_ITYPE)
{
    __shared__ float4 s_rel[16 * 16];
    __shared__ float4 s_inter[8 * 16];

    for (int j = threadIdx.x; j < N_REL * 16; j += blockDim.x)
        s_rel[j] = rel4[j];
    for (int j = threadIdx.x; j < N_ITYPE * 16; j += blockDim.x)
        s_inter[j] = inter4[j];
    __syncthreads();

    int c = threadIdx.x & 7;
    int g0    = (int)(((long long)blockIdx.x * blockDim.x + threadIdx.x) >> 3);
    int gstep = (int)(((long long)gridDim.x * blockDim.x) >> 3);

    float* ent_agg = out;
    float* usr_agg = out + (long long)N_ENT * DD;

    // ---- Phase 1: KG edges (branch-free loop) ----
    #pragma unroll 2
    for (int e = g0; e < E_KG; e += gstep) {
        int head = eidx[e];
        int tail = eidx[E_KG + e];
        int rt   = etype[e] - 1;
        const float4* nrow = ent4 + (long long)tail * 16;
        float4 nv0 = nrow[c];
        float4 nv1 = nrow[c + 8];
        float4 rv0 = s_rel[rt * 16 + c];
        float4 rv1 = s_rel[rt * 16 + c + 8];
        float p = dot4(nv0, rv0) + dot4(nv1, rv1);
        #pragma unroll
        for (int o = 4; o > 0; o >>= 1)
            p += __shfl_xor_sync(0xffffffffu, p, o);
        float ex = __expf(p * 0.125f);
        float* dst = ent_agg + (long long)head * DD;
        red_add_v4(dst + c * 4,
                   make_float4(nv0.x * ex, nv0.y * ex, nv0.z * ex, nv0.w * ex));
        red_add_v4(dst + (c + 8) * 4,
                   make_float4(nv1.x * ex, nv1.y * ex, nv1.z * ex, nv1.w * ex));
        if (c == 0) {
            g_score[e] = ex;
            atomicAdd(&g_ssum[head], ex);
        }
    }

    // ---- Phase 2: UI edges (branch-free loop) ----
    #pragma unroll 2
    for (int i = g0; i < E_UI; i += gstep) {
        int u  = uidx[i];
        int it = iidx[i];
        int ty = itype[i];
        const float4* irow = ent4 + (long long)it * 16;
        const float4* urow = usr4 + (long long)u * 16;
        float4 iv0 = irow[c];
        float4 iv1 = irow[c + 8];
        float4 uv0 = urow[c];
        float4 uv1 = urow[c + 8];
        float4 tv0 = s_inter[ty * 16 + c];
        float4 tv1 = s_inter[ty * 16 + c + 8];
        float p = dot4x3(iv0, uv0, tv0) + dot4x3(iv1, uv1, tv1);
        #pragma unroll
        for (int o = 4; o > 0; o >>= 1)
            p += __shfl_xor_sync(0xffffffffu, p, o);
        float ex = __expf(p);
        float* dst = usr_agg + (long long)u * DD;
        red_add_v4(dst + c * 4,
                   make_float4(iv0.x * ex, iv0.y * ex, iv0.z * ex, iv0.w * ex));
        red_add_v4(dst + (c + 8) * 4,
                   make_float4(iv1.x * ex, iv1.y * ex, iv1.z * ex, iv1.w * ex));
        if (c == 0) {
            g_score[E_KG + i] = ex;
            atomicAdd(&g_ssum[N_ENT + u], ex);
        }
    }
}

// ---------------------------------------------------------------------------
// K2: merged tail. [0, n4): normalize agg rows; [n4, n4+T): edge weights.
// ---------------------------------------------------------------------------
__global__ void k_tail(float4* __restrict__ out4, int n4,
                       const int* __restrict__ eidx,
                       const int* __restrict__ uidx,
                       float* __restrict__ out,
                       int E_KG, int E_UI, int N_ENT, int N_USR)
{
    int i = blockIdx.x * blockDim.x + threadIdx.x;
    if (i < n4) {
        int seg = i >> 4;
        float s = g_ssum[seg];
        float inv = (s > 0.0f) ? __frcp_rn(s) : 0.0f;
        float4 v = out4[i];
        v.x *= inv; v.y *= inv; v.z *= inv; v.w *= inv;
        out4[i] = v;
    } else {
        int e = i - n4;
        int T = E_KG + E_UI;
        if (e >= T) return;
        float* att_out = out + (long long)(N_ENT + N_USR) * DD;
        float* w1_out  = att_out + E_UI;
        if (e < E_KG) {
            int head = eidx[e];
            w1_out[e] = g_score[e] * __frcp_rn(g_ssum[head]);
        } else {
            int j = e - E_KG;
            int u = uidx[j];
            att_out[j] = g_score[e] * __frcp_rn(g_ssum[N_ENT + u]);
        }
    }
}

// ---------------------------------------------------------------------------
extern "C" void kernel_launch(void* const* d_in, const int* in_sizes, int n_in,
                              void* d_out, int out_size)
{
    const float4* ent4   = (const float4*)d_in[0];
    const float4* usr4   = (const float4*)d_in[1];
    const float4* inter4 = (const float4*)d_in[2];
    const float4* rel4   = (const float4*)d_in[3];
    const int* eidx  = (const int*)d_in[4];
    const int* etype = (const int*)d_in[5];
    const int* uidx  = (const int*)d_in[6];
    const int* iidx  = (const int*)d_in[7];
    const int* itype = (const int*)d_in[8];
    float* out = (float*)d_out;

    int N_ENT   = in_sizes[0] / DD;
    int N_USR   = in_sizes[1] / DD;
    int N_ITYPE = in_sizes[2] / DD;
    int N_REL   = in_sizes[3] / DD;
    int E_KG    = in_sizes[5];
    int E_UI    = in_sizes[6];
    int T = E_KG + E_UI;
    int n_agg = (N_ENT + N_USR) * DD;
    int n_seg = N_ENT + N_USR;
    int n4 = n_agg / 4;

    const int B = 256;

    k_init<<<4096, B>>>((float4*)out, n4, n_seg);

    // persistent grid: 148 SMs x 16 blocks (2 CTAs/SM resident, balanced waves)
    k_fused<<<2368, B>>>(ent4, usr4, inter4, rel4,
                         eidx, etype, uidx, iidx, itype,
                         out, E_KG, E_UI, N_ENT, N_USR, N_REL, N_ITYPE);

    int tail_work = n4 + T;
    k_tail<<<(tail_work + B - 1) / B, B>>>((float4*)out, n4, eidx, uidx, out,
                                           E_KG, E_UI, N_ENT, N_USR);
}

// round 17
// speedup vs baseline: 1.4251x; 1.0792x over previous
#include <cuda_runtime.h>
#include <cuda_bf16.h>
#include <cstdint>

#define DD 64

#define MAX_E_TOTAL 2000000      // E_KG + E_UI
#define MAX_SEG     160000       // N_ENT + N_USR

// -------- device scratch (no allocations allowed) --------
static __device__ float g_score[MAX_E_TOTAL];   // holds ex = exp(score)
static __device__ float g_ssum [MAX_SEG];

// Fire-and-forget vector reduction. NO "memory" clobber: the only reader of
// the accumulators is k_tail (next kernel launch), and register dataflow
// already orders each RED after its own source loads. Without the clobber,
// ptxas may hoist the next iteration's gather loads above this RED,
// increasing memory-level parallelism across loop iterations.
__device__ __forceinline__ void red_add_v4(float* p, float4 v) {
    asm volatile("red.global.add.v4.f32 [%0], {%1,%2,%3,%4};"
                 :: "l"(p), "f"(v.x), "f"(v.y), "f"(v.z), "f"(v.w));
}
__device__ __forceinline__ float dot4(float4 a, float4 b) {
    return a.x * b.x + a.y * b.y + a.z * b.z + a.w * b.w;
}
__device__ __forceinline__ float dot4x3(float4 a, float4 b, float4 c) {
    return a.x * b.x * c.x + a.y * b.y * c.y + a.z * b.z * c.z + a.w * b.w * c.w;
}

// ---------------------------------------------------------------------------
// K0: init — zero agg outputs (float4) and segment sums
// ---------------------------------------------------------------------------
__global__ void k_init(float4* out4, int n4, int n_seg) {
    int i = blockIdx.x * blockDim.x + threadIdx.x;
    int stride = gridDim.x * blockDim.x;
    float4 z = make_float4(0.f, 0.f, 0.f, 0.f);
    for (int j = i; j < n4; j += stride) out4[j] = z;
    for (int j = i; j < n_seg; j += stride) g_ssum[j] = 0.0f;
}

// ---------------------------------------------------------------------------
// K1: FUSED heavy pass. 8 threads per edge, 2x float4 per thread (R9 layout:
//   single interleaved grid-stride loop, persistent 2048-block grid,
//   rel/inter tables staged in smem once per block).
// ---------------------------------------------------------------------------
__global__ void __launch_bounds__(256)
k_fused(const float4* __restrict__ ent4,
        const float4* __restrict__ usr4,
        const float4* __restrict__ inter4,
        const float4* __restrict__ rel4,
        const int* __restrict__ eidx,      // [2, E_KG]
        const int* __restrict__ etype,     // [E_KG]
        const int* __restrict__ uidx,      // [E_UI]
        const int* __restrict__ iidx,      // [E_UI]
        const int* __restrict__ itype,     // [E_UI]
        float* __restrict__ out,
        int E_KG, int E_UI, int N_ENT, int N_USR,
        int N_REL, int N_ITYPE)
{
    __shared__ float4 s_rel[16 * 16];
    __shared__ float4 s_inter[8 * 16];

    for (int j = threadIdx.x; j < N_REL * 16; j += blockDim.x)
        s_rel[j] = rel4[j];
    for (int j = threadIdx.x; j < N_ITYPE * 16; j += blockDim.x)
        s_inter[j] = inter4[j];
    __syncthreads();

    int T = E_KG + E_UI;
    int c = threadIdx.x & 7;
    int e0    = (int)(((long long)blockIdx.x * blockDim.x + threadIdx.x) >> 3);
    int estep = (int)(((long long)gridDim.x * blockDim.x) >> 3);

    float* ent_agg = out;
    float* usr_agg = out + (long long)N_ENT * DD;

    for (int e = e0; e < T; e += estep) {
        if (e < E_KG) {
            int head = eidx[e];
            int tail = eidx[E_KG + e];
            int rt   = etype[e] - 1;
            const float4* nrow = ent4 + (long long)tail * 16;
            float4 nv0 = nrow[c];
            float4 nv1 = nrow[c + 8];
            float4 rv0 = s_rel[rt * 16 + c];
            float4 rv1 = s_rel[rt * 16 + c + 8];
            float p = dot4(nv0, rv0) + dot4(nv1, rv1);
            #pragma unroll
            for (int o = 4; o > 0; o >>= 1)
                p += __shfl_xor_sync(0xffffffffu, p, o);
            float ex = __expf(p * 0.125f);
            float* dst = ent_agg + (long long)head * DD;
            red_add_v4(dst + c * 4,
                       make_float4(nv0.x * ex, nv0.y * ex, nv0.z * ex, nv0.w * ex));
            red_add_v4(dst + (c + 8) * 4,
                       make_float4(nv1.x * ex, nv1.y * ex, nv1.z * ex, nv1.w * ex));
            if (c == 0) {
                g_score[e] = ex;
                atomicAdd(&g_ssum[head], ex);
            }
        } else {
            int i  = e - E_KG;
            int u  = uidx[i];
            int it = iidx[i];
            int ty = itype[i];
            const float4* irow = ent4 + (long long)it * 16;
            const float4* urow = usr4 + (long long)u * 16;
            float4 iv0 = irow[c];
            float4 iv1 = irow[c + 8];
            float4 uv0 = urow[c];
            float4 uv1 = urow[c + 8];
            float4 tv0 = s_inter[ty * 16 + c];
            float4 tv1 = s_inter[ty * 16 + c + 8];
            float p = dot4x3(iv0, uv0, tv0) + dot4x3(iv1, uv1, tv1);
            #pragma unroll
            for (int o = 4; o > 0; o >>= 1)
                p += __shfl_xor_sync(0xffffffffu, p, o);
            float ex = __expf(p);
            float* dst = usr_agg + (long long)u * DD;
            red_add_v4(dst + c * 4,
                       make_float4(iv0.x * ex, iv0.y * ex, iv0.z * ex, iv0.w * ex));
            red_add_v4(dst + (c + 8) * 4,
                       make_float4(iv1.x * ex, iv1.y * ex, iv1.z * ex, iv1.w * ex));
            if (c == 0) {
                g_score[e] = ex;
                atomicAdd(&g_ssum[N_ENT + u], ex);
            }
        }
    }
}

// ---------------------------------------------------------------------------
// K2: merged tail. [0, n4): normalize agg rows; [n4, n4+T): edge weights.
// ---------------------------------------------------------------------------
__global__ void k_tail(float4* __restrict__ out4, int n4,
                       const int* __restrict__ eidx,
                       const int* __restrict__ uidx,
                       float* __restrict__ out,
                       int E_KG, int E_UI, int N_ENT, int N_USR)
{
    int i = blockIdx.x * blockDim.x + threadIdx.x;
    if (i < n4) {
        int seg = i >> 4;
        float s = g_ssum[seg];
        float inv = (s > 0.0f) ? __frcp_rn(s) : 0.0f;
        float4 v = out4[i];
        v.x *= inv; v.y *= inv; v.z *= inv; v.w *= inv;
        out4[i] = v;
    } else {
        int e = i - n4;
        int T = E_KG + E_UI;
        if (e >= T) return;
        float* att_out = out + (long long)(N_ENT + N_USR) * DD;
        float* w1_out  = att_out + E_UI;
        if (e < E_KG) {
            int head = eidx[e];
            w1_out[e] = g_score[e] * __frcp_rn(g_ssum[head]);
        } else {
            int j = e - E_KG;
            int u = uidx[j];
            att_out[j] = g_score[e] * __frcp_rn(g_ssum[N_ENT + u]);
        }
    }
}

// ---------------------------------------------------------------------------
extern "C" void kernel_launch(void* const* d_in, const int* in_sizes, int n_in,
                              void* d_out, int out_size)
{
    const float4* ent4   = (const float4*)d_in[0];
    const float4* usr4   = (const float4*)d_in[1];
    const float4* inter4 = (const float4*)d_in[2];
    const float4* rel4   = (const float4*)d_in[3];
    const int* eidx  = (const int*)d_in[4];
    const int* etype = (const int*)d_in[5];
    const int* uidx  = (const int*)d_in[6];
    const int* iidx  = (const int*)d_in[7];
    const int* itype = (const int*)d_in[8];
    float* out = (float*)d_out;

    int N_ENT   = in_sizes[0] / DD;
    int N_USR   = in_sizes[1] / DD;
    int N_ITYPE = in_sizes[2] / DD;
    int N_REL   = in_sizes[3] / DD;
    int E_KG    = in_sizes[5];
    int E_UI    = in_sizes[6];
    int T = E_KG + E_UI;
    int n_agg = (N_ENT + N_USR) * DD;
    int n_seg = N_ENT + N_USR;
    int n4 = n_agg / 4;

    const int B = 256;

    k_init<<<2048, B>>>((float4*)out, n4, n_seg);

    // persistent grid: 2048 blocks, each warp grid-strides over edge-groups
    k_fused<<<2048, B>>>(ent4, usr4, inter4, rel4,
                         eidx, etype, uidx, iidx, itype,
                         out, E_KG, E_UI, N_ENT, N_USR, N_REL, N_ITYPE);

    int tail_work = n4 + T;
    k_tail<<<(tail_work + B - 1) / B, B>>>((float4*)out, n4, eidx, uidx, out,
                                           E_KG, E_UI, N_ENT, N_USR);
}